// round 12
// baseline (speedup 1.0000x reference)
#include <cuda_runtime.h>
#include <math.h>

#define NB 64
#define V 256
#define F 64
#define C 64
#define ALPHA_C 0.1f
#define YSZ (NB * V * F)

typedef unsigned long long ull;

// ---------------- packed f32x2 helpers (mega1 y-path) ----------------
__device__ __forceinline__ ull pk2(float v) {
    ull r;
    asm("mov.b64 %0, {%1, %1};" : "=l"(r) : "f"(v));
    return r;
}
__device__ __forceinline__ ull add2(ull a, ull b) {
    ull r;
    asm("add.rn.f32x2 %0, %1, %2;" : "=l"(r) : "l"(a), "l"(b));
    return r;
}
__device__ __forceinline__ ull fma2(ull a, ull b, ull c) {
    ull r;
    asm("fma.rn.f32x2 %0, %1, %2, %3;" : "=l"(r) : "l"(a), "l"(b), "l"(c));
    return r;
}
__device__ __forceinline__ void upk2(ull v, float& lo, float& hi) {
    asm("mov.b64 {%0, %1}, %2;" : "=f"(lo), "=f"(hi) : "l"(v));
}
#define ABS2_MASK 0x7FFFFFFF7FFFFFFFULL

// ---------------- tf32 mma / ldmatrix helpers ----------------
__device__ __forceinline__ unsigned cvt_tf32(float f) {
    unsigned r;
    asm("cvt.rna.tf32.f32 %0, %1;" : "=r"(r) : "f"(f));
    return r;
}
__device__ __forceinline__ void mma_tf32(float* c,
    unsigned a0, unsigned a1, unsigned a2, unsigned a3,
    unsigned b0, unsigned b1) {
    asm("mma.sync.aligned.m16n8k8.row.col.f32.tf32.tf32.f32 "
        "{%0,%1,%2,%3}, {%4,%5,%6,%7}, {%8,%9}, {%0,%1,%2,%3};"
        : "+f"(c[0]), "+f"(c[1]), "+f"(c[2]), "+f"(c[3])
        : "r"(a0), "r"(a1), "r"(a2), "r"(a3), "r"(b0), "r"(b1));
}
__device__ __forceinline__ void ldm_x4(unsigned& r0, unsigned& r1,
                                       unsigned& r2, unsigned& r3, unsigned addr) {
    asm volatile("ldmatrix.sync.aligned.m8n8.x4.shared.b16 {%0,%1,%2,%3}, [%4];"
        : "=r"(r0), "=r"(r1), "=r"(r2), "=r"(r3) : "r"(addr));
}

// ---------------- scratch (no allocations allowed) ----------------
__device__ float g_pc[NB * 4 * V];
__device__ float g_pA[NB * 4 * V];
__device__ float g_pB[NB * 4 * V];
__device__ float g_r[NB * V];
__device__ float g_lossP[NB];
__device__ float g_Y[3 * YSZ];        // Y0 = x@(th0-th2), Y1 = x@(-th1), Y2 = x@(2*th2)
__device__ unsigned g_Z1t[NB * C * V];  // tf32(r*Y1) transposed [c][k]
__device__ unsigned g_Z2t[NB * C * V];  // tf32(r^2*Y2) transposed [c][k]
__device__ int g_cntG;                // global arrival counter (zero-init; self-resetting)

__constant__ int c_IT[10] = {0, 0, 0, 0, 1, 1, 1, 2, 2, 3};
__constant__ int c_JT[10] = {0, 1, 2, 3, 1, 2, 3, 2, 3, 3};

#define N_PW 640
#define N_YG 768
#define POOL_F 10880
#define P_CC 4352
#define P_AC (4352 + 1088)
#define P_BC (4352 + 2176)
#define P_CR (4352 + 3264)
#define P_AR (4352 + 4352)
#define P_BR (4352 + 5440)

// ---------------- mega kernel 1: pairwise (idx<640) + y_gemm (idx>=640) ----------------
__global__ __launch_bounds__(256) void mega1_kernel(
    const float* __restrict__ x, const float* __restrict__ a,
    const float* __restrict__ theta, float* __restrict__ s_out) {
    __shared__ __align__(16) float pool[POOL_F];

    const int t = threadIdx.x;
    const int tx = t & 15, ty = t >> 4;

    if (blockIdx.x >= N_PW) {
        // ================= y_gemm part =================
        int idx = blockIdx.x - N_PW;
        const int it = idx & 3;
        const int m = (idx >> 2) % 3;
        const int b = idx / 12;
        const int i0 = it * 64;
        float (*sW)[64] = (float(*)[64])pool;
        float (*sX)[68] = (float(*)[68])(pool + 4096);
        const float* xb = x + b * V * F;

        for (int q = t; q < 64 * 16; q += 256) {
            int f = q >> 4;
            int c4 = (q & 15) * 4;
            float4 v;
            if (m == 0) {
                float4 t0 = *(const float4*)&theta[(0 * F + f) * C + c4];
                float4 t2 = *(const float4*)&theta[(2 * F + f) * C + c4];
                v = make_float4(t0.x - t2.x, t0.y - t2.y, t0.z - t2.z, t0.w - t2.w);
            } else if (m == 1) {
                float4 t1 = *(const float4*)&theta[(1 * F + f) * C + c4];
                v = make_float4(-t1.x, -t1.y, -t1.z, -t1.w);
            } else {
                float4 t2 = *(const float4*)&theta[(2 * F + f) * C + c4];
                v = make_float4(2.f * t2.x, 2.f * t2.y, 2.f * t2.z, 2.f * t2.w);
            }
            *(float4*)&sW[f][c4] = v;
        }
        for (int q = t; q < 64 * 16; q += 256) {
            int i = q >> 4;
            int f4 = (q & 15) * 4;
            float4 v = *(const float4*)&xb[(i0 + i) * F + f4];
            sX[f4 + 0][i] = v.x;
            sX[f4 + 1][i] = v.y;
            sX[f4 + 2][i] = v.z;
            sX[f4 + 3][i] = v.w;
        }
        __syncthreads();

        ull acc2[4][2];
#pragma unroll
        for (int ii = 0; ii < 4; ii++)
#pragma unroll
            for (int p = 0; p < 2; p++) acc2[ii][p] = 0ULL;

#pragma unroll 4
        for (int k = 0; k < 64; k++) {
            float4 xa = *(const float4*)&sX[k][ty * 4];
            ulonglong2 wp = *(const ulonglong2*)&sW[k][tx * 4];
            float xv[4] = {xa.x, xa.y, xa.z, xa.w};
#pragma unroll
            for (int ii = 0; ii < 4; ii++) {
                ull xv2 = pk2(xv[ii]);
                acc2[ii][0] = fma2(xv2, wp.x, acc2[ii][0]);
                acc2[ii][1] = fma2(xv2, wp.y, acc2[ii][1]);
            }
        }

        float* y = g_Y + m * YSZ + b * V * F;
#pragma unroll
        for (int ii = 0; ii < 4; ii++) {
            int row = i0 + ty * 4 + ii;
            float4 o;
            upk2(acc2[ii][0], o.x, o.y);
            upk2(acc2[ii][1], o.z, o.w);
            *(float4*)&y[row * F + tx * 4] = o;
        }
        return;
    }

    // ================= pairwise part =================
    const int b = blockIdx.x / 10;
    const int tile = blockIdx.x % 10;
    const int it = c_IT[tile], jt = c_JT[tile];
    const int i0 = it * 64, j0 = jt * 64;
    const bool offdiag = (it != jt);
    const float* xb = x + b * V * F;

    float (*xi_t)[68] = (float(*)[68])pool;
    float (*xj_t)[68] = (float(*)[68])(pool + 4352);
    float* a_s = pool + 8704;

    for (int e = t; e < 64 * F; e += 256) {
        int row = e >> 6;
        int f = e & 63;
        xi_t[f][row] = xb[(i0 + row) * F + f];
        xj_t[f][row] = -xb[(j0 + row) * F + f];
    }
    if (t < F) a_s[t] = a[t];
    __syncthreads();

    ull sc2[4][2], dd2[4][2];
#pragma unroll
    for (int ii = 0; ii < 4; ii++)
#pragma unroll
        for (int p = 0; p < 2; p++) { sc2[ii][p] = 0ULL; dd2[ii][p] = 0ULL; }

#pragma unroll 4
    for (int f = 0; f < F; f++) {
        float4 xi4 = *(const float4*)&xi_t[f][ty * 4];
        ulonglong2 xjp = *(const ulonglong2*)&xj_t[f][tx * 4];
        float xiv[4] = {xi4.x, xi4.y, xi4.z, xi4.w};
        ull af2 = pk2(a_s[f]);
#pragma unroll
        for (int ii = 0; ii < 4; ii++) {
            ull xi2 = pk2(xiv[ii]);
            ull d0 = add2(xi2, xjp.x);
            ull d1 = add2(xi2, xjp.y);
            sc2[ii][0] = fma2(d0 & ABS2_MASK, af2, sc2[ii][0]);
            sc2[ii][1] = fma2(d1 & ABS2_MASK, af2, sc2[ii][1]);
            dd2[ii][0] = fma2(d0, d0, dd2[ii][0]);
            dd2[ii][1] = fma2(d1, d1, dd2[ii][1]);
        }
    }

    float sc[4][4], dd[4][4];
#pragma unroll
    for (int ii = 0; ii < 4; ii++)
#pragma unroll
        for (int p = 0; p < 2; p++) {
            upk2(sc2[ii][p], sc[ii][2 * p], sc[ii][2 * p + 1]);
            upk2(dd2[ii][p], dd[ii][2 * p], dd[ii][2 * p + 1]);
        }

    float tm[4][4];
    float cpart[4] = {0.f, 0.f, 0.f, 0.f};
    float Apart[4] = {0.f, 0.f, 0.f, 0.f};
    float Bpart[4] = {0.f, 0.f, 0.f, 0.f};
    float rc[4] = {0.f, 0.f, 0.f, 0.f};
    float rA[4] = {0.f, 0.f, 0.f, 0.f};
    float rB[4] = {0.f, 0.f, 0.f, 0.f};

#pragma unroll
    for (int ii = 0; ii < 4; ii++) {
#pragma unroll
        for (int jj = 0; jj < 4; jj++) {
            float tmp = __expf(-fmaxf(sc[ii][jj], 0.f));
            tm[ii][jj] = tmp;
            float t2 = tmp * tmp;
            float td = tmp * dd[ii][jj];
            cpart[jj] += tmp; Apart[jj] += t2; Bpart[jj] += td;
            rc[ii] += tmp;    rA[ii] += t2;    rB[ii] += td;
        }
    }

    __syncthreads();

    float* sb = s_out + (size_t)b * V * V;
#pragma unroll
    for (int ii = 0; ii < 4; ii++) {
        *(float4*)&sb[(i0 + ty * 4 + ii) * V + j0 + tx * 4] =
            make_float4(tm[ii][0], tm[ii][1], tm[ii][2], tm[ii][3]);
    }

#pragma unroll
    for (int jj = 0; jj < 4; jj++) {
        int col = tx * 4 + jj;
        pool[P_CC + col * 17 + ty] = cpart[jj];
        pool[P_AC + col * 17 + ty] = Apart[jj];
        pool[P_BC + col * 17 + ty] = Bpart[jj];
    }
    if (offdiag) {
#pragma unroll
        for (int ii = 0; ii < 4; ii++) {
            int row = ty * 4 + ii;
            pool[P_CR + row * 17 + tx] = rc[ii];
            pool[P_AR + row * 17 + tx] = rA[ii];
            pool[P_BR + row * 17 + tx] = rB[ii];
        }
#pragma unroll
        for (int jj = 0; jj < 4; jj++) {
            *(float4*)&xi_t[tx * 4 + jj][ty * 4] =
                make_float4(tm[0][jj], tm[1][jj], tm[2][jj], tm[3][jj]);
        }
    }
    __syncthreads();

    if (t < 64) {
        float cs = 0.f, As = 0.f, Bs = 0.f;
#pragma unroll
        for (int u = 0; u < 16; u++) {
            cs += pool[P_CC + t * 17 + u];
            As += pool[P_AC + t * 17 + u];
            Bs += pool[P_BC + t * 17 + u];
        }
        int bc = (b * 4 + it) * V + j0 + t;
        g_pc[bc] = cs; g_pA[bc] = As; g_pB[bc] = Bs;
        if (offdiag) {
            float cr = 0.f, Ar = 0.f, Br = 0.f;
#pragma unroll
            for (int u = 0; u < 16; u++) {
                cr += pool[P_CR + t * 17 + u];
                Ar += pool[P_AR + t * 17 + u];
                Br += pool[P_BR + t * 17 + u];
            }
            int br = (b * 4 + jt) * V + i0 + t;
            g_pc[br] = cr; g_pA[br] = Ar; g_pB[br] = Br;
        }
    }

    if (offdiag) {
        for (int e = t; e < 64 * 16; e += 256) {
            int row = e >> 4;
            int c4 = (e & 15) * 4;
            *(float4*)&sb[(j0 + row) * V + i0 + c4] = *(float4*)&xi_t[row][c4];
        }
    }
}

// ---------------- prep kernel: r, loss partial, Z1t/Z2t (tf32, transposed [c][k]) ----------------
// Grid (64 b), 256 threads.
__global__ __launch_bounds__(256) void prep_kernel() {
    __shared__ float sRr[256];
    __shared__ unsigned tile[64][33];
    __shared__ float red[256];

    const int b = blockIdx.x;
    const int t = threadIdx.x;

    {
        int base = b * 4 * V + t;
        float cs = g_pc[base] + g_pc[base + V] + g_pc[base + 2 * V] + g_pc[base + 3 * V];
        float A = g_pA[base] + g_pA[base + V] + g_pA[base + 2 * V] + g_pA[base + 3 * V];
        float B = g_pB[base] + g_pB[base + V] + g_pB[base + 2 * V] + g_pB[base + 3 * V];
        float r = 1.0f / cs;
        sRr[t] = r;
        g_r[b * V + t] = r;
        red[t] = A * r * r + ALPHA_C * B * r;
    }
    __syncthreads();
    for (int s = 128; s > 0; s >>= 1) {
        if (t < s) red[t] += red[t + s];
        __syncthreads();
    }
    if (t == 0) g_lossP[b] = red[0];

    const float* Ysrc[2] = {g_Y + 1 * YSZ + b * V * F, g_Y + 2 * YSZ + b * V * F};
    unsigned* Zdst[2] = {g_Z1t + b * C * V, g_Z2t + b * C * V};

#pragma unroll
    for (int arr = 0; arr < 2; arr++) {
        const float* Y = Ysrc[arr];
        unsigned* Z = Zdst[arr];
        for (int ch = 0; ch < 8; ch++) {
            int kc0 = ch * 32;
            __syncthreads();  // protect tile against previous out-phase readers
            for (int e = t; e < 512; e += 256) {
                int k = e >> 4;
                int c4 = (e & 15) * 4;
                float rk = sRr[kc0 + k];
                if (arr) rk *= rk;
                float4 v = *(const float4*)&Y[(kc0 + k) * F + c4];
                tile[c4 + 0][k] = cvt_tf32(v.x * rk);
                tile[c4 + 1][k] = cvt_tf32(v.y * rk);
                tile[c4 + 2][k] = cvt_tf32(v.z * rk);
                tile[c4 + 3][k] = cvt_tf32(v.w * rk);
            }
            __syncthreads();
            for (int e = t; e < 2048; e += 256) {
                int c = e >> 5;
                int k = e & 31;
                Z[c * V + kc0 + k] = tile[c][k];  // coalesced: 128B per c-row
            }
        }
    }
}

// ---------------- stage 3 (tf32 + LDSM): gcn = relu(Y0 + tmp@Z1 + tmp^2@Z2) ----------------
// Grid (8 it, 64 b) = 512 blocks; 256 thr (8 warps); block tile 32(i) x 64(c), K=256.
// Z1t/Z2t pre-scaled/converted/transposed by prep -> staging is a pure vector copy.
__global__ __launch_bounds__(256) void tf32_gemm_kernel(
    float* __restrict__ s_out, float* __restrict__ gcn, float* __restrict__ out_loss) {
    __shared__ unsigned sA [32][36];  // cvt_tf32(tmp), [i][k], 32-k chunk
    __shared__ unsigned sA2[32][36];  // cvt_tf32(tmp^2)
    __shared__ unsigned sZ1[64][36];  // [c][k]
    __shared__ unsigned sZ2[64][36];  // [c][k]
    __shared__ float sR[256];

    const int b = blockIdx.y, it = blockIdx.x;
    const int i0 = it * 32;
    const int t = threadIdx.x;
    const int w = t >> 5, l = t & 31;
    const int g = l >> 2, q4 = l & 3;
    const int wr = (w & 1) * 16;
    const int nc0 = (w >> 1) * 16;

    sR[t] = g_r[b * V + t];
    __syncthreads();

    const int msel = l >> 3, mrow = l & 7;
    const unsigned aOff = ((wr + (msel & 1) * 8 + mrow) * 36 + (msel >> 1) * 4) * 4;
    const unsigned aBase  = (unsigned)__cvta_generic_to_shared(sA)  + aOff;
    const unsigned a2Base = (unsigned)__cvta_generic_to_shared(sA2) + aOff;
    const unsigned zOff = ((nc0 + (msel >> 1) * 8 + mrow) * 36 + (msel & 1) * 4) * 4;
    const unsigned z1Base = (unsigned)__cvta_generic_to_shared(sZ1) + zOff;
    const unsigned z2Base = (unsigned)__cvta_generic_to_shared(sZ2) + zOff;

    float* sb = s_out + (size_t)b * V * V;
    const unsigned* z1g = g_Z1t + b * C * V;
    const unsigned* z2g = g_Z2t + b * C * V;

    float acc[2][4];
#pragma unroll
    for (int nt = 0; nt < 2; nt++)
#pragma unroll
        for (int u = 0; u < 4; u++) acc[nt][u] = 0.f;

    for (int ch = 0; ch < 8; ch++) {
        int kc0 = ch * 32;
        // stage A / A^2, normalize + write back s: 32 rows x 32 k
        {
            int i = t >> 3;
            int k4 = (t & 7) * 4;
            float* addr = &sb[(i0 + i) * V + kc0 + k4];
            float4 v = *(const float4*)addr;
            float4 rv = *(const float4*)&sR[kc0 + k4];
            *(float4*)addr = make_float4(v.x * rv.x, v.y * rv.y, v.z * rv.z, v.w * rv.w);
            sA[i][k4 + 0] = cvt_tf32(v.x);
            sA[i][k4 + 1] = cvt_tf32(v.y);
            sA[i][k4 + 2] = cvt_tf32(v.z);
            sA[i][k4 + 3] = cvt_tf32(v.w);
            sA2[i][k4 + 0] = cvt_tf32(v.x * v.x);
            sA2[i][k4 + 1] = cvt_tf32(v.y * v.y);
            sA2[i][k4 + 2] = cvt_tf32(v.z * v.z);
            sA2[i][k4 + 3] = cvt_tf32(v.w * v.w);
        }
        // stage Z1/Z2: pure vector copy from pre-transposed global
        for (int e = t; e < 512; e += 256) {
            int c = e >> 3;
            int k4 = (e & 7) * 4;
            *(uint4*)&sZ1[c][k4] = *(const uint4*)&z1g[c * V + kc0 + k4];
            *(uint4*)&sZ2[c][k4] = *(const uint4*)&z2g[c * V + kc0 + k4];
        }
        __syncthreads();

#pragma unroll
        for (int kk = 0; kk < 4; kk++) {
            unsigned koff = kk * 32;
            unsigned a0, a1, a2, a3, p0, p1, p2, p3;
            unsigned u0, u1, u2, u3, v0, v1, v2, v3;
            ldm_x4(a0, a1, a2, a3, aBase + koff);
            ldm_x4(p0, p1, p2, p3, a2Base + koff);
            ldm_x4(u0, u1, u2, u3, z1Base + koff);
            ldm_x4(v0, v1, v2, v3, z2Base + koff);
            mma_tf32(acc[0], a0, a1, a2, a3, u0, u1);
            mma_tf32(acc[0], p0, p1, p2, p3, v0, v1);
            mma_tf32(acc[1], a0, a1, a2, a3, u2, u3);
            mma_tf32(acc[1], p0, p1, p2, p3, v2, v3);
        }
        __syncthreads();
    }

    // epilogue: gcn = relu(Y0 + acc)
    const float* y0 = g_Y + b * V * F;
    int r0 = i0 + wr + g, r1 = r0 + 8;
#pragma unroll
    for (int nt = 0; nt < 2; nt++) {
        int col = nc0 + nt * 8 + 2 * q4;
        float2 ya = *(const float2*)&y0[r0 * F + col];
        float2 yb = *(const float2*)&y0[r1 * F + col];
        float2 oa = make_float2(fmaxf(acc[nt][0] + ya.x, 0.f), fmaxf(acc[nt][1] + ya.y, 0.f));
        float2 ob = make_float2(fmaxf(acc[nt][2] + yb.x, 0.f), fmaxf(acc[nt][3] + yb.y, 0.f));
        *(float2*)&gcn[b * V * C + r0 * C + col] = oa;
        *(float2*)&gcn[b * V * C + r1 * C + col] = ob;
    }

    // loss finisher: globally last block writes the scalar
    __threadfence();
    __syncthreads();
    if (t == 0) {
        int og = atomicAdd(&g_cntG, 1);
        if (og == NB * 8 - 1) {
            g_cntG = 0;  // reset for next graph replay
            __threadfence();
            float acc2 = 0.f;
#pragma unroll 8
            for (int i = 0; i < NB; i++) acc2 += g_lossP[i];
            *out_loss = acc2;
        }
    }
}

// ---------------- launch ----------------
extern "C" void kernel_launch(void* const* d_in, const int* in_sizes, int n_in,
                              void* d_out, int out_size) {
    const float* x = (const float*)d_in[0];      // (64,256,64)
    const float* a = (const float*)d_in[1];      // (64,)
    const float* theta = (const float*)d_in[2];  // (3,64,64)

    float* out = (float*)d_out;
    float* gcn = out;                                 // NB*V*C
    float* s_out = out + (size_t)NB * V * C;          // NB*V*V
    float* loss = out + (size_t)NB * V * C + (size_t)NB * V * V;  // 1

    mega1_kernel<<<N_PW + N_YG, 256>>>(x, a, theta, s_out);

    prep_kernel<<<NB, 256>>>();

    dim3 gB(8, NB);
    tf32_gemm_kernel<<<gB, 256>>>(s_out, gcn, loss);
}

// round 14
// speedup vs baseline: 1.2108x; 1.2108x over previous
#include <cuda_runtime.h>
#include <math.h>

#define NB 64
#define V 256
#define F 64
#define C 64
#define ALPHA_C 0.1f
#define YSZ (NB * V * F)

typedef unsigned long long ull;

// ---------------- packed f32x2 helpers (mega1 y-path) ----------------
__device__ __forceinline__ ull pk2(float v) {
    ull r;
    asm("mov.b64 %0, {%1, %1};" : "=l"(r) : "f"(v));
    return r;
}
__device__ __forceinline__ ull add2(ull a, ull b) {
    ull r;
    asm("add.rn.f32x2 %0, %1, %2;" : "=l"(r) : "l"(a), "l"(b));
    return r;
}
__device__ __forceinline__ ull fma2(ull a, ull b, ull c) {
    ull r;
    asm("fma.rn.f32x2 %0, %1, %2, %3;" : "=l"(r) : "l"(a), "l"(b), "l"(c));
    return r;
}
__device__ __forceinline__ void upk2(ull v, float& lo, float& hi) {
    asm("mov.b64 {%0, %1}, %2;" : "=f"(lo), "=f"(hi) : "l"(v));
}
#define ABS2_MASK 0x7FFFFFFF7FFFFFFFULL

// ---------------- tf32 mma helpers ----------------
__device__ __forceinline__ unsigned cvt_tf32(float f) {
    unsigned r;
    asm("cvt.rna.tf32.f32 %0, %1;" : "=r"(r) : "f"(f));
    return r;
}
__device__ __forceinline__ void mma_tf32(float* c,
    unsigned a0, unsigned a1, unsigned a2, unsigned a3,
    unsigned b0, unsigned b1) {
    asm("mma.sync.aligned.m16n8k8.row.col.f32.tf32.tf32.f32 "
        "{%0,%1,%2,%3}, {%4,%5,%6,%7}, {%8,%9}, {%0,%1,%2,%3};"
        : "+f"(c[0]), "+f"(c[1]), "+f"(c[2]), "+f"(c[3])
        : "r"(a0), "r"(a1), "r"(a2), "r"(a3), "r"(b0), "r"(b1));
}

// ---------------- scratch (no allocations allowed) ----------------
__device__ float g_pc[NB * 4 * V];
__device__ float g_pA[NB * 4 * V];
__device__ float g_pB[NB * 4 * V];
__device__ float g_lossP[NB];
__device__ float g_Y[3 * YSZ];   // Y0 = x@(th0-th2), Y1 = x@(-th1), Y2 = x@(2*th2)
__device__ int g_cntG;           // global arrival counter (zero-init; self-resetting)

__constant__ int c_IT[10] = {0, 0, 0, 0, 1, 1, 1, 2, 2, 3};
__constant__ int c_JT[10] = {0, 1, 2, 3, 1, 2, 3, 2, 3, 3};

#define N_PW 640
#define N_YG 768
#define POOL_F 10880
#define P_CC 4352
#define P_AC (4352 + 1088)
#define P_BC (4352 + 2176)
#define P_CR (4352 + 3264)
#define P_AR (4352 + 4352)
#define P_BR (4352 + 5440)

// ---------------- mega kernel 1: pairwise (idx<640) + y_gemm (idx>=640) ----------------
__global__ __launch_bounds__(256) void mega1_kernel(
    const float* __restrict__ x, const float* __restrict__ a,
    const float* __restrict__ theta, float* __restrict__ s_out) {
    __shared__ __align__(16) float pool[POOL_F];

    const int t = threadIdx.x;
    const int tx = t & 15, ty = t >> 4;

    if (blockIdx.x >= N_PW) {
        // ================= y_gemm part =================
        int idx = blockIdx.x - N_PW;
        const int it = idx & 3;
        const int m = (idx >> 2) % 3;
        const int b = idx / 12;
        const int i0 = it * 64;
        float (*sW)[64] = (float(*)[64])pool;
        float (*sX)[68] = (float(*)[68])(pool + 4096);
        const float* xb = x + b * V * F;

        for (int q = t; q < 64 * 16; q += 256) {
            int f = q >> 4;
            int c4 = (q & 15) * 4;
            float4 v;
            if (m == 0) {
                float4 t0 = *(const float4*)&theta[(0 * F + f) * C + c4];
                float4 t2 = *(const float4*)&theta[(2 * F + f) * C + c4];
                v = make_float4(t0.x - t2.x, t0.y - t2.y, t0.z - t2.z, t0.w - t2.w);
            } else if (m == 1) {
                float4 t1 = *(const float4*)&theta[(1 * F + f) * C + c4];
                v = make_float4(-t1.x, -t1.y, -t1.z, -t1.w);
            } else {
                float4 t2 = *(const float4*)&theta[(2 * F + f) * C + c4];
                v = make_float4(2.f * t2.x, 2.f * t2.y, 2.f * t2.z, 2.f * t2.w);
            }
            *(float4*)&sW[f][c4] = v;
        }
        for (int q = t; q < 64 * 16; q += 256) {
            int i = q >> 4;
            int f4 = (q & 15) * 4;
            float4 v = *(const float4*)&xb[(i0 + i) * F + f4];
            sX[f4 + 0][i] = v.x;
            sX[f4 + 1][i] = v.y;
            sX[f4 + 2][i] = v.z;
            sX[f4 + 3][i] = v.w;
        }
        __syncthreads();

        ull acc2[4][2];
#pragma unroll
        for (int ii = 0; ii < 4; ii++)
#pragma unroll
            for (int p = 0; p < 2; p++) acc2[ii][p] = 0ULL;

#pragma unroll 4
        for (int k = 0; k < 64; k++) {
            float4 xa = *(const float4*)&sX[k][ty * 4];
            ulonglong2 wp = *(const ulonglong2*)&sW[k][tx * 4];
            float xv[4] = {xa.x, xa.y, xa.z, xa.w};
#pragma unroll
            for (int ii = 0; ii < 4; ii++) {
                ull xv2 = pk2(xv[ii]);
                acc2[ii][0] = fma2(xv2, wp.x, acc2[ii][0]);
                acc2[ii][1] = fma2(xv2, wp.y, acc2[ii][1]);
            }
        }

        float* y = g_Y + m * YSZ + b * V * F;
#pragma unroll
        for (int ii = 0; ii < 4; ii++) {
            int row = i0 + ty * 4 + ii;
            float4 o;
            upk2(acc2[ii][0], o.x, o.y);
            upk2(acc2[ii][1], o.z, o.w);
            *(float4*)&y[row * F + tx * 4] = o;
        }
        return;
    }

    // ================= pairwise part =================
    const int b = blockIdx.x / 10;
    const int tile = blockIdx.x % 10;
    const int it = c_IT[tile], jt = c_JT[tile];
    const int i0 = it * 64, j0 = jt * 64;
    const bool offdiag = (it != jt);
    const float* xb = x + b * V * F;

    float (*xi_t)[68] = (float(*)[68])pool;
    float (*xj_t)[68] = (float(*)[68])(pool + 4352);
    float* a_s = pool + 8704;

    for (int e = t; e < 64 * F; e += 256) {
        int row = e >> 6;
        int f = e & 63;
        xi_t[f][row] = xb[(i0 + row) * F + f];
        xj_t[f][row] = -xb[(j0 + row) * F + f];
    }
    if (t < F) a_s[t] = a[t];
    __syncthreads();

    ull sc2[4][2], dd2[4][2];
#pragma unroll
    for (int ii = 0; ii < 4; ii++)
#pragma unroll
        for (int p = 0; p < 2; p++) { sc2[ii][p] = 0ULL; dd2[ii][p] = 0ULL; }

#pragma unroll 4
    for (int f = 0; f < F; f++) {
        float4 xi4 = *(const float4*)&xi_t[f][ty * 4];
        ulonglong2 xjp = *(const ulonglong2*)&xj_t[f][tx * 4];
        float xiv[4] = {xi4.x, xi4.y, xi4.z, xi4.w};
        ull af2 = pk2(a_s[f]);
#pragma unroll
        for (int ii = 0; ii < 4; ii++) {
            ull xi2 = pk2(xiv[ii]);
            ull d0 = add2(xi2, xjp.x);
            ull d1 = add2(xi2, xjp.y);
            sc2[ii][0] = fma2(d0 & ABS2_MASK, af2, sc2[ii][0]);
            sc2[ii][1] = fma2(d1 & ABS2_MASK, af2, sc2[ii][1]);
            dd2[ii][0] = fma2(d0, d0, dd2[ii][0]);
            dd2[ii][1] = fma2(d1, d1, dd2[ii][1]);
        }
    }

    float sc[4][4], dd[4][4];
#pragma unroll
    for (int ii = 0; ii < 4; ii++)
#pragma unroll
        for (int p = 0; p < 2; p++) {
            upk2(sc2[ii][p], sc[ii][2 * p], sc[ii][2 * p + 1]);
            upk2(dd2[ii][p], dd[ii][2 * p], dd[ii][2 * p + 1]);
        }

    float tm[4][4];
    float cpart[4] = {0.f, 0.f, 0.f, 0.f};
    float Apart[4] = {0.f, 0.f, 0.f, 0.f};
    float Bpart[4] = {0.f, 0.f, 0.f, 0.f};
    float rc[4] = {0.f, 0.f, 0.f, 0.f};
    float rA[4] = {0.f, 0.f, 0.f, 0.f};
    float rB[4] = {0.f, 0.f, 0.f, 0.f};

#pragma unroll
    for (int ii = 0; ii < 4; ii++) {
#pragma unroll
        for (int jj = 0; jj < 4; jj++) {
            float tmp = __expf(-fmaxf(sc[ii][jj], 0.f));
            tm[ii][jj] = tmp;
            float t2 = tmp * tmp;
            float td = tmp * dd[ii][jj];
            cpart[jj] += tmp; Apart[jj] += t2; Bpart[jj] += td;
            rc[ii] += tmp;    rA[ii] += t2;    rB[ii] += td;
        }
    }

    __syncthreads();

    float* sb = s_out + (size_t)b * V * V;
#pragma unroll
    for (int ii = 0; ii < 4; ii++) {
        *(float4*)&sb[(i0 + ty * 4 + ii) * V + j0 + tx * 4] =
            make_float4(tm[ii][0], tm[ii][1], tm[ii][2], tm[ii][3]);
    }

#pragma unroll
    for (int jj = 0; jj < 4; jj++) {
        int col = tx * 4 + jj;
        pool[P_CC + col * 17 + ty] = cpart[jj];
        pool[P_AC + col * 17 + ty] = Apart[jj];
        pool[P_BC + col * 17 + ty] = Bpart[jj];
    }
    if (offdiag) {
#pragma unroll
        for (int ii = 0; ii < 4; ii++) {
            int row = ty * 4 + ii;
            pool[P_CR + row * 17 + tx] = rc[ii];
            pool[P_AR + row * 17 + tx] = rA[ii];
            pool[P_BR + row * 17 + tx] = rB[ii];
        }
#pragma unroll
        for (int jj = 0; jj < 4; jj++) {
            *(float4*)&xi_t[tx * 4 + jj][ty * 4] =
                make_float4(tm[0][jj], tm[1][jj], tm[2][jj], tm[3][jj]);
        }
    }
    __syncthreads();

    if (t < 64) {
        float cs = 0.f, As = 0.f, Bs = 0.f;
#pragma unroll
        for (int u = 0; u < 16; u++) {
            cs += pool[P_CC + t * 17 + u];
            As += pool[P_AC + t * 17 + u];
            Bs += pool[P_BC + t * 17 + u];
        }
        int bc = (b * 4 + it) * V + j0 + t;
        g_pc[bc] = cs; g_pA[bc] = As; g_pB[bc] = Bs;
        if (offdiag) {
            float cr = 0.f, Ar = 0.f, Br = 0.f;
#pragma unroll
            for (int u = 0; u < 16; u++) {
                cr += pool[P_CR + t * 17 + u];
                Ar += pool[P_AR + t * 17 + u];
                Br += pool[P_BR + t * 17 + u];
            }
            int br = (b * 4 + jt) * V + i0 + t;
            g_pc[br] = cr; g_pA[br] = Ar; g_pB[br] = Br;
        }
    }

    if (offdiag) {
        for (int e = t; e < 64 * 16; e += 256) {
            int row = e >> 4;
            int c4 = (e & 15) * 4;
            *(float4*)&sb[(j0 + row) * V + i0 + c4] = *(float4*)&xi_t[row][c4];
        }
    }
}

// ---------------- stage 2 (tf32 tensor, R10 config + hoisted A^2) ----------------
// gcn = relu(Y0 + tmp@Z1 + tmp^2@Z2), Z1 = diag(r)Y1, Z2 = diag(r^2)Y2.
// Grid (4 it, 64 b), 256 thr (8 warps). Warp tile: 16 rows x 32 cols.
// Also normalizes s in place, computes loss.
__global__ __launch_bounds__(256) void tf32_gemm_kernel(
    float* __restrict__ s_out, float* __restrict__ gcn, float* __restrict__ out_loss) {
    __shared__ unsigned sA [64][36];  // cvt_tf32(tmp), rows i0..i0+63, 32-k chunk
    __shared__ unsigned sA2[64][36];  // cvt_tf32(tmp^2)  (hoisted from inner loop)
    __shared__ unsigned sZ1[32][72];  // cvt_tf32(r*Y1) [k][c]
    __shared__ unsigned sZ2[32][72];  // cvt_tf32(r^2*Y2) [k][c]
    __shared__ float sR[256];

    const int b = blockIdx.y, it = blockIdx.x;
    const int i0 = it * 64;
    const int t = threadIdx.x;
    const int w = t >> 5, l = t & 31;
    const int g = l >> 2, q4 = l & 3;
    const int wr = (w & 3) * 16;    // warp row base in tile
    const int nc0 = (w >> 2) * 32;  // warp col base

    // per-column reciprocal for all 256 k
    {
        int base = b * 4 * V + t;
        float cs = g_pc[base] + g_pc[base + V] + g_pc[base + 2 * V] + g_pc[base + 3 * V];
        float r = 1.0f / cs;
        sR[t] = r;
        if (it == 0) {
            float A = g_pA[base] + g_pA[base + V] + g_pA[base + 2 * V] + g_pA[base + 3 * V];
            float B = g_pB[base] + g_pB[base + V] + g_pB[base + 2 * V] + g_pB[base + 3 * V];
            ((float*)sZ1)[t] = A * r * r + ALPHA_C * B * r;
        }
    }
    if (it == 0) {
        float* red = (float*)sZ1;
        __syncthreads();
        for (int s = 128; s > 0; s >>= 1) {
            if (t < s) red[t] += red[t + s];
            __syncthreads();
        }
        if (t == 0) g_lossP[b] = red[0];
    }
    __syncthreads();

    float* sb = s_out + (size_t)b * V * V;
    const float* y1g = g_Y + 1 * YSZ + b * V * F;
    const float* y2g = g_Y + 2 * YSZ + b * V * F;

    float acc[4][4];
#pragma unroll
    for (int nt = 0; nt < 4; nt++)
#pragma unroll
        for (int u = 0; u < 4; u++) acc[nt][u] = 0.f;

    for (int ch = 0; ch < 8; ch++) {
        int kc0 = ch * 32;
        // stage A / A^2 (tmp), normalize + write back s
        for (int e = t; e < 512; e += 256) {
            int i = e >> 3;
            int k4 = (e & 7) * 4;
            float* addr = &sb[(i0 + i) * V + kc0 + k4];
            float4 v = *(const float4*)addr;
            float4 rv = *(const float4*)&sR[kc0 + k4];
            *(float4*)addr = make_float4(v.x * rv.x, v.y * rv.y, v.z * rv.z, v.w * rv.w);
            sA[i][k4 + 0] = cvt_tf32(v.x);
            sA[i][k4 + 1] = cvt_tf32(v.y);
            sA[i][k4 + 2] = cvt_tf32(v.z);
            sA[i][k4 + 3] = cvt_tf32(v.w);
            sA2[i][k4 + 0] = cvt_tf32(v.x * v.x);
            sA2[i][k4 + 1] = cvt_tf32(v.y * v.y);
            sA2[i][k4 + 2] = cvt_tf32(v.z * v.z);
            sA2[i][k4 + 3] = cvt_tf32(v.w * v.w);
        }
        // stage Z1/Z2
        for (int e = t; e < 512; e += 256) {
            int k = e >> 4;
            int c4 = (e & 15) * 4;
            float r = sR[kc0 + k];
            float r2 = r * r;
            float4 v1 = *(const float4*)&y1g[(kc0 + k) * F + c4];
            float4 v2 = *(const float4*)&y2g[(kc0 + k) * F + c4];
            sZ1[k][c4 + 0] = cvt_tf32(v1.x * r);
            sZ1[k][c4 + 1] = cvt_tf32(v1.y * r);
            sZ1[k][c4 + 2] = cvt_tf32(v1.z * r);
            sZ1[k][c4 + 3] = cvt_tf32(v1.w * r);
            sZ2[k][c4 + 0] = cvt_tf32(v2.x * r2);
            sZ2[k][c4 + 1] = cvt_tf32(v2.y * r2);
            sZ2[k][c4 + 2] = cvt_tf32(v2.z * r2);
            sZ2[k][c4 + 3] = cvt_tf32(v2.w * r2);
        }
        __syncthreads();

#pragma unroll
        for (int k8 = 0; k8 < 4; k8++) {
            int kc = k8 * 8;
            int ra = wr + g;
            unsigned a0 = sA[ra][kc + q4];
            unsigned a1 = sA[ra + 8][kc + q4];
            unsigned a2 = sA[ra][kc + 4 + q4];
            unsigned a3 = sA[ra + 8][kc + 4 + q4];
            unsigned q0 = sA2[ra][kc + q4];
            unsigned q1 = sA2[ra + 8][kc + q4];
            unsigned q2 = sA2[ra][kc + 4 + q4];
            unsigned q3 = sA2[ra + 8][kc + 4 + q4];
#pragma unroll
            for (int nt = 0; nt < 4; nt++) {
                int ncol = nc0 + nt * 8 + g;
                unsigned b0 = sZ1[kc + q4][ncol];
                unsigned b1 = sZ1[kc + 4 + q4][ncol];
                mma_tf32(acc[nt], a0, a1, a2, a3, b0, b1);
                unsigned c0 = sZ2[kc + q4][ncol];
                unsigned c1 = sZ2[kc + 4 + q4][ncol];
                mma_tf32(acc[nt], q0, q1, q2, q3, c0, c1);
            }
        }
        __syncthreads();
    }

    // epilogue: gcn = relu(Y0 + acc)
    const float* y0 = g_Y + b * V * F;
    int r0 = i0 + wr + g, r1 = r0 + 8;
#pragma unroll
    for (int nt = 0; nt < 4; nt++) {
        int col = nc0 + nt * 8 + 2 * q4;
        float2 ya = *(const float2*)&y0[r0 * F + col];
        float2 yb = *(const float2*)&y0[r1 * F + col];
        float2 oa = make_float2(fmaxf(acc[nt][0] + ya.x, 0.f), fmaxf(acc[nt][1] + ya.y, 0.f));
        float2 ob = make_float2(fmaxf(acc[nt][2] + yb.x, 0.f), fmaxf(acc[nt][3] + yb.y, 0.f));
        *(float2*)&gcn[b * V * C + r0 * C + col] = oa;
        *(float2*)&gcn[b * V * C + r1 * C + col] = ob;
    }

    // loss finisher: globally last block writes the scalar
    __threadfence();
    __syncthreads();
    if (t == 0) {
        int og = atomicAdd(&g_cntG, 1);
        if (og == NB * 4 - 1) {
            g_cntG = 0;  // reset for next graph replay
            __threadfence();
            float acc2 = 0.f;
#pragma unroll 8
            for (int i = 0; i < NB; i++) acc2 += g_lossP[i];
            *out_loss = acc2;
        }
    }
}

// ---------------- launch ----------------
extern "C" void kernel_launch(void* const* d_in, const int* in_sizes, int n_in,
                              void* d_out, int out_size) {
    const float* x = (const float*)d_in[0];      // (64,256,64)
    const float* a = (const float*)d_in[1];      // (64,)
    const float* theta = (const float*)d_in[2];  // (3,64,64)

    float* out = (float*)d_out;
    float* gcn = out;                                 // NB*V*C
    float* s_out = out + (size_t)NB * V * C;          // NB*V*V
    float* loss = out + (size_t)NB * V * C + (size_t)NB * V * V;  // 1

    mega1_kernel<<<N_PW + N_YG, 256>>>(x, a, theta, s_out);

    dim3 gB(4, NB);
    tf32_gemm_kernel<<<gB, 256>>>(s_out, gcn, loss);
}